// round 8
// baseline (speedup 1.0000x reference)
#include <cuda_runtime.h>

#define PI_D 3.141592653589793238462643383279502884
#define SCALING_F 0.008164965809277260f   // 1/sqrt(24*16*20^4/64^2) = 1/sqrt(15000)

// Compact l-major layout for m>=0 spectra:
//   per l: (l+1) rows (m = 0..l) x (2l+1) cols (ni = n+l).  Total NC = 5530.
#define NC 5530

#define CMADD(acc, a, b) { acc.x += (a).x*(b).x - (a).y*(b).y; acc.y += (a).x*(b).y + (a).y*(b).x; }
#define CROT(w, s) { float _x = (w).x*(s).x - (w).y*(s).y; (w).y = (w).x*(s).y + (w).y*(s).x; (w).x = _x; }

// ---------------- scratch (device globals; no allocation allowed) ----------------
static __device__ double dd_df[41];                  // factorials
static __device__ double dd_wq[128];
static __device__ float  dd_ws2[128 * 400];          // [b][col]
static __device__ float2 dd_Fk[24 * 400];            // [p][col]
static __device__ float  dd_dinv[40 * NC];           // [b][cidx]  (2l+1)*d^l_{m,n}, m>=0
static __device__ float2 dd_XF[16 * 16 * 20 * 128];  // [(z*16+i)][m(0..19)][b]
static __device__ float2 dd_G[16 * 16 * 400];        // [(z*16+i)][col]
static __device__ float2 dd_Y[32 * 16 * 400];        // conj(y)*SCALING: [o][i][col]  (i-major)
static __device__ float2 dd_ZL[512 * NC];            // [(z*32+o)][cidx], m>=0 only
static __device__ float2 dd_tw40[40];                // e^{+2pi i t/40}
static __device__ float2 dd_tw128[128];              // e^{+2pi i t/128}

// ---------------- Wigner small-d via factorial-ratio recurrence (fp64) ----------------
__device__ double wigner_d_dev(int l, int m, int n, double beta) {
    double cb = cos(0.5 * beta), sb = sin(0.5 * beta);
    int s0 = (n - m) > 0 ? (n - m) : 0;
    int s1 = (l + n) < (l - m) ? (l + n) : (l - m);
    if (s1 < s0) return 0.0;
    double pref = sqrt(dd_df[l + m]) * sqrt(dd_df[l - m]) * sqrt(dd_df[l + n]) * sqrt(dd_df[l - n]);
    double t = pref / (dd_df[l + n - s0] * dd_df[s0] * dd_df[m - n + s0] * dd_df[l - m - s0]);
    int ec = 2 * l + n - m - 2 * s0;
    int es = m - n + 2 * s0;
    for (int k = 0; k < ec; k++) t *= cb;
    for (int k = 0; k < es; k++) t *= sb;
    if ((m - n + s0) & 1) t = -t;
    double v = t;
    double r2 = (sb * sb) / (cb * cb);
    for (int s = s0; s < s1; s++) {
        t *= -r2 * (double)((l + n - s) * (l - m - s)) / (double)((s + 1) * (m - n + s + 1));
        v += t;
    }
    return v;
}

__device__ __forceinline__ int col_to_l(int col) {
    int l = (int)sqrtf((float)col);
    while ((l + 1) * (l + 1) <= col) l++;
    while (l * l > col) l--;
    return l;
}

// decode compact cidx -> (l, m>=0, ni)
__device__ __forceinline__ void decode_c(int c, int& l, int& m, int& ni) {
    l = 0;
    while (c >= (l + 1) * (2 * l + 1)) { c -= (l + 1) * (2 * l + 1); l++; }
    int w = 2 * l + 1;
    m = c / w;
    ni = c - m * w;
}

// ---------------- stage 0: tables ----------------
__global__ void k_setup() {
    int t = threadIdx.x;
    if (t < 41) {
        double f = 1.0;
        for (int k = 2; k <= t; k++) f *= (double)k;
        dd_df[t] = f;
    }
    if (t < 40) {
        double a = 2.0 * PI_D * t / 40.0;
        dd_tw40[t] = make_float2((float)cos(a), (float)sin(a));
    }
    if (t < 128) {
        double a = 2.0 * PI_D * t / 128.0;
        dd_tw128[t] = make_float2((float)cos(a), (float)sin(a));
        double th = PI_D * (2 * t + 1) / 256.0;
        double s = 0.0;
        for (int k = 0; k < 64; k++) s += sin((2.0 * k + 1.0) * th) / (2.0 * k + 1.0);
        dd_wq[t] = (2.0 / 64.0) * sin(th) * s;
    }
}

__global__ void k_ws2() {
    int idx = blockIdx.x * blockDim.x + threadIdx.x;
    if (idx >= 128 * 400) return;
    int b = idx / 400, col = idx - b * 400;
    int l = col_to_l(col);
    int m = col - l * l - l;
    double beta = PI_D * (2 * b + 1) / 256.0;
    dd_ws2[idx] = (float)(wigner_d_dev(l, m, 0, beta) * dd_wq[b]);
}

__global__ void k_Fk() {
    int idx = blockIdx.x * blockDim.x + threadIdx.x;
    if (idx >= 24 * 400) return;
    int p = idx / 400, col = idx - p * 400;
    int l = col_to_l(col);
    int m = col - l * l - l;
    double beta = (double)(p / 8 + 1) * PI_D / 24.0;
    double alpha = (double)(p % 8) * (PI_D / 4.0);
    double d = wigner_d_dev(l, m, 0, beta);
    dd_Fk[idx] = make_float2((float)(d * cos(m * alpha)), (float)(-d * sin(m * alpha)));
}

__global__ void k_dinv() {
    int idx = blockIdx.x * blockDim.x + threadIdx.x;
    if (idx >= 40 * NC) return;
    int b = idx / NC, c = idx - b * NC;
    int l, m, ni;
    decode_c(c, l, m, ni);
    double beta = PI_D * (2 * b + 1) / 80.0;
    dd_dinv[idx] = (float)((double)(2 * l + 1) * wigner_d_dev(l, m, ni - l, beta));
}

// ---------------- stage 1: alpha-DFT (20 non-negative bins), one block per (z,i) ----------------
__global__ void k_XF(const float* __restrict__ x) {
    __shared__ float2 twT[128 * 20];   // [a][m], e^{-2pi i m a/128} stored as (cos,-sin)
    __shared__ float  xs[12][129];     // padded rows
    int zi = blockIdx.x;
    int t = threadIdx.x;               // 256 threads
    for (int i = t; i < 128 * 20; i += 256) {
        int a = i / 20, mi = i - a * 20;
        float2 w = dd_tw128[(a * mi) & 127];
        twT[i] = make_float2(w.x, -w.y);
    }
    const float* xp = x + (size_t)zi * 128 * 128;
    for (int chunk = 0; chunk < 11; chunk++) {
        int b0 = chunk * 12;
        __syncthreads();
        for (int i = t; i < 12 * 128; i += 256) {
            int r = i >> 7, a = i & 127;
            if (b0 + r < 128) xs[r][a] = xp[(size_t)(b0 + r) * 128 + a];
        }
        __syncthreads();
        if (t < 240) {
            int r = t / 20, mi = t - r * 20;
            int b = b0 + r;
            if (b < 128) {
                float re = 0.f, im = 0.f;
                #pragma unroll 8
                for (int a = 0; a < 128; a++) {
                    float v = xs[r][a];
                    float2 w = twT[a * 20 + mi];
                    re += v * w.x;
                    im += v * w.y;
                }
                dd_XF[((size_t)zi * 20 + mi) * 128 + b] = make_float2(re, im);
            }
        }
    }
}

// ---------------- stage 2: S2 analysis (negative m via conjugate) ----------------
__global__ void k_G() {
    int idx = blockIdx.x * blockDim.x + threadIdx.x;
    if (idx >= 16 * 16 * 400) return;
    int zi = idx / 400, col = idx - zi * 400;
    int l = col_to_l(col);
    int m = col - l * l - l;
    int am = m < 0 ? -m : m;
    float sgn = m < 0 ? -1.f : 1.f;
    const float2* xf = &dd_XF[((size_t)zi * 20 + am) * 128];
    float re = 0.f, im = 0.f;
    #pragma unroll 4
    for (int b = 0; b < 128; b++) {
        float w = dd_ws2[b * 400 + col];
        float2 v = xf[b];
        re += w * v.x;
        im += w * v.y;
    }
    dd_G[idx] = make_float2(re, sgn * im);
}

// ---------------- stage 3: kernel spectrum (store conj * SCALING), i-major layout ----------------
__global__ void k_Y(const float* __restrict__ ker) {
    int idx = blockIdx.x * blockDim.x + threadIdx.x;
    if (idx >= 32 * 16 * 400) return;
    int o = idx / 6400;
    int r = idx - o * 6400;
    int i = r / 400, col = r - i * 400;
    const float* kp = ker + ((size_t)i * 32 + o) * 24;
    float re = 0.f, im = 0.f;
    #pragma unroll
    for (int p = 0; p < 24; p++) {
        float2 f = dd_Fk[p * 400 + col];
        float kv = kp[p];
        re += kv * f.x;
        im += kv * f.y;
    }
    dd_Y[idx] = make_float2(SCALING_F * re, -SCALING_F * im);
}

// ---------------- stage 4: per-(z,o) SO(3) spectrum (m>=0 only) ----------------
__global__ void k_ZL() {
    extern __shared__ float2 smzl[];
    float2* Gs = smzl;            // 6400: [i][col] for this z
    float2* Ys = smzl + 6400;     // 6400: [i][col] for this o (already conj)
    int bi = blockIdx.x;
    int z = bi >> 5, o = bi & 31;
    int tid = threadIdx.x;
    for (int i = tid; i < 6400; i += blockDim.x) {
        Gs[i] = dd_G[z * 6400 + i];
        Ys[i] = dd_Y[o * 6400 + i];
    }
    __syncthreads();
    for (int cidx = tid; cidx < NC; cidx += blockDim.x) {
        int l, m, ni;
        decode_c(cidx, l, m, ni);
        int colm = l * l + l + m;      // m >= 0
        int coln = l * l + ni;
        float re = 0.f, im = 0.f;
        #pragma unroll
        for (int i = 0; i < 16; i++) {
            float2 a = Gs[i * 400 + colm];
            float2 yb = Ys[i * 400 + coln];
            re += a.x * yb.x - a.y * yb.y;
            im += a.x * yb.y + a.y * yb.x;
        }
        dd_ZL[(size_t)bi * NC + cidx] = make_float2(re, im);
    }
}

// ---------------- stage 5+6 fused: beta synthesis + Hermitian 2D inverse DFT ----------------
// grid = 512 (z,o) x 5 pair-groups; each block: 2 chunks x 2 beta-pairs (b, 39-b).
// Reflection symmetry d^l_{m,n}(pi-b) = (-1)^{l+m} d^l_{m,-n}(b) -> one dinv row per pair.
// Uniform-l M-loop (coalesced dinv), 2m x 4g T-tiles, 4a x 2g f-tiles, parity folds.
// SMEM: zls (5530) | Ms (4*820) | Ts (4*820) | twl (40) = 97040 B.
__global__ void __launch_bounds__(256) k_OUT(const float* __restrict__ bias, float* __restrict__ out) {
    extern __shared__ float2 sm[];
    float2* zls = sm;                       // 5530
    float2* Ms  = sm + NC;                  // 4*820, row stride 41
    float2* Ts  = Ms + 4 * 820;             // 4*820, row stride 41
    float2* twl = Ts + 4 * 820;             // 40
    int bi = blockIdx.x / 5;
    int group = blockIdx.x - bi * 5;        // 0..4 -> pairs group*4 .. group*4+3
    int o = bi & 31;
    int tid = threadIdx.x;
    for (int i = tid; i < NC; i += 256) zls[i] = dd_ZL[(size_t)bi * NC + i];
    if (tid < 40) twl[tid] = dd_tw40[tid];
    float bv = bias[o];
    __syncthreads();
    float* outp = out + (size_t)bi * 64000;

    for (int chunk = 0; chunk < 2; chunk++) {
        int pair0 = group * 4 + chunk * 2;   // two pairs: pair0, pair0+1
        // beta map: bl 0 -> pair0, 1 -> 39-pair0, 2 -> pair0+1, 3 -> 39-(pair0+1)
        // ---- M-stage: per item (pr, m, nni): one dinv row -> M[b] and M[39-b] ----
        for (int p = tid; p < 2 * 780; p += 256) {
            int pr = p / 780, q = p - pr * 780;
            int b = pair0 + pr;
            int m = q / 39, nni = q - m * 39;
            int n = nni - 19;
            int an = n < 0 ? -n : n;
            int lmin = m > an ? m : an;
            const float* dv = &dd_dinv[(size_t)b * NC];
            float reA = 0.f, imA = 0.f, reB = 0.f, imB = 0.f;
            int cum = 0;
            #pragma unroll
            for (int l = 0; l < 20; l++) {
                int w = 2 * l + 1;
                if (l >= lmin) {
                    int base = cum + m * w;
                    int cidx  = base + (n + l);
                    int cidx2 = base + (l - n);
                    float d = dv[cidx];
                    float s = ((l + m) & 1) ? -d : d;
                    float2 zA = zls[cidx];
                    float2 zB = zls[cidx2];
                    reA += zA.x * d;  imA += zA.y * d;
                    reB += zB.x * s;  imB += zB.y * s;
                }
                cum += (l + 1) * w;
            }
            Ms[((2 * pr) * 20 + m) * 41 + nni] = make_float2(reA, imA);
            Ms[((2 * pr + 1) * 20 + m) * 41 + (38 - nni)] = make_float2(reB, imB);
        }
        __syncthreads();
        // ---- T-stage: T[m,g] = sum_n M[m,n] e^{+i n g th}; g and g+20 via n-parity ----
        // 200 tiles: bl(4) x tm(10) x tg(5); tile = 2m x 4g
        if (tid < 200) {
            int bl = tid / 50, r = tid - bl * 50;
            int tm = r / 5, tg = r - tm * 5;
            int m0 = tm * 2, g0 = tg * 4;
            const float2* M0 = &Ms[(bl * 20 + m0) * 41];
            const float2* M1 = M0 + 41;
            float2 w0 = twl[(21 * g0) % 40];
            float2 w1 = twl[(21 * (g0 + 1)) % 40];
            float2 w2 = twl[(21 * (g0 + 2)) % 40];
            float2 w3 = twl[(21 * (g0 + 3)) % 40];
            float2 s0 = twl[g0], s1 = twl[g0 + 1], s2 = twl[g0 + 2], s3 = twl[g0 + 3];
            float2 aE0[4] = {{0,0},{0,0},{0,0},{0,0}}, aO0[4] = {{0,0},{0,0},{0,0},{0,0}};
            float2 aE1[4] = {{0,0},{0,0},{0,0},{0,0}}, aO1[4] = {{0,0},{0,0},{0,0},{0,0}};
            #pragma unroll
            for (int nn = 0; nn < 39; nn++) {
                float2 mv0 = M0[nn], mv1 = M1[nn];
                if (nn & 1) {   // n = nn-19 even
                    CMADD(aE0[0], mv0, w0); CMADD(aE0[1], mv0, w1); CMADD(aE0[2], mv0, w2); CMADD(aE0[3], mv0, w3);
                    CMADD(aE1[0], mv1, w0); CMADD(aE1[1], mv1, w1); CMADD(aE1[2], mv1, w2); CMADD(aE1[3], mv1, w3);
                } else {        // n odd
                    CMADD(aO0[0], mv0, w0); CMADD(aO0[1], mv0, w1); CMADD(aO0[2], mv0, w2); CMADD(aO0[3], mv0, w3);
                    CMADD(aO1[0], mv1, w0); CMADD(aO1[1], mv1, w1); CMADD(aO1[2], mv1, w2); CMADD(aO1[3], mv1, w3);
                }
                CROT(w0, s0); CROT(w1, s1); CROT(w2, s2); CROT(w3, s3);
            }
            float2* T0 = &Ts[(bl * 20 + m0) * 41];
            float2* T1 = T0 + 41;
            #pragma unroll
            for (int j = 0; j < 4; j++) {
                T0[g0 + j]      = make_float2(aE0[j].x + aO0[j].x, aE0[j].y + aO0[j].y);
                T0[g0 + j + 20] = make_float2(aE0[j].x - aO0[j].x, aE0[j].y - aO0[j].y);
                T1[g0 + j]      = make_float2(aE1[j].x + aO1[j].x, aE1[j].y + aO1[j].y);
                T1[g0 + j + 20] = make_float2(aE1[j].x - aO1[j].x, aE1[j].y - aO1[j].y);
            }
        }
        __syncthreads();
        // ---- f-stage: f[a,g] = bv + T[0,g].re + 2 sum_{m>=1} Re(T[m,g] e^{i m a th});
        //      a and a+20 via m-parity. 400 tiles: bl(4) x ta(5) x tg(20); tile = 4a x 2g
        for (int tt = tid; tt < 400; tt += 256) {
            int bl = tt / 100, r = tt - bl * 100;
            int ta = r / 20, tg = r - ta * 20;
            int a0 = ta * 4, g0 = tg * 2;
            const float2* Tb = &Ts[(bl * 20) * 41];
            float2 w[4] = {twl[a0], twl[a0 + 1], twl[a0 + 2], twl[a0 + 3]};
            float2 sst[4] = {w[0], w[1], w[2], w[3]};
            float sE[4][2] = {{0,0},{0,0},{0,0},{0,0}};
            float sO[4][2] = {{0,0},{0,0},{0,0},{0,0}};
            #pragma unroll
            for (int m = 1; m < 20; m++) {
                float2 t0 = Tb[m * 41 + g0];
                float2 t1 = Tb[m * 41 + g0 + 1];
                #pragma unroll
                for (int j = 0; j < 4; j++) {
                    float v0 = t0.x * w[j].x - t0.y * w[j].y;
                    float v1 = t1.x * w[j].x - t1.y * w[j].y;
                    if (m & 1) { sO[j][0] += v0; sO[j][1] += v1; }
                    else       { sE[j][0] += v0; sE[j][1] += v1; }
                    CROT(w[j], sst[j]);
                }
            }
            int pr2 = bl >> 1;
            int beta = (bl & 1) ? (39 - (pair0 + pr2)) : (pair0 + pr2);
            float base0 = bv + Tb[g0].x;
            float base1 = bv + Tb[g0 + 1].x;
            float* op = outp + (size_t)beta * 1600;
            #pragma unroll
            for (int j = 0; j < 4; j++) {
                *(float2*)&op[(a0 + j) * 40 + g0] =
                    make_float2(base0 + 2.f * (sE[j][0] + sO[j][0]), base1 + 2.f * (sE[j][1] + sO[j][1]));
                *(float2*)&op[(a0 + j + 20) * 40 + g0] =
                    make_float2(base0 + 2.f * (sE[j][0] - sO[j][0]), base1 + 2.f * (sE[j][1] - sO[j][1]));
            }
        }
        __syncthreads();
    }
}

// ---------------- launcher ----------------
extern "C" void kernel_launch(void* const* d_in, const int* in_sizes, int n_in,
                              void* d_out, int out_size) {
    const float* x    = (const float*)d_in[0];   // [16,16,128,128]
    const float* ker  = (const float*)d_in[1];   // [16,32,24]
    const float* bias = (const float*)d_in[2];   // [32]
    float* out = (float*)d_out;                  // [16,32,40,40,40]

    cudaFuncSetAttribute(k_ZL,  cudaFuncAttributeMaxDynamicSharedMemorySize, 102400);
    cudaFuncSetAttribute(k_OUT, cudaFuncAttributeMaxDynamicSharedMemorySize, 97040);

    k_setup<<<1, 128>>>();
    k_ws2 <<<200, 256>>>();
    k_Fk  <<<38, 256>>>();
    k_dinv<<<(40 * NC + 255) / 256, 256>>>();
    k_XF  <<<256, 256>>>(x);
    k_G   <<<400, 256>>>();
    k_Y   <<<800, 256>>>(ker);
    k_ZL  <<<512, 256, 102400>>>();
    k_OUT <<<2560, 256, 97040>>>(bias, out);
}

// round 10
// speedup vs baseline: 1.1013x; 1.1013x over previous
#include <cuda_runtime.h>

#define PI_D 3.141592653589793238462643383279502884
#define SCALING_F 0.008164965809277260f   // 1/sqrt(24*16*20^4/64^2) = 1/sqrt(15000)

// Compact l-major layout for m>=0 spectra:
//   per l: (l+1) rows (m = 0..l) x (2l+1) cols (ni = n+l).  Total NC = 5530.
#define NC 5530

#define CMADD(acc, a, b) { acc.x += (a).x*(b).x - (a).y*(b).y; acc.y += (a).x*(b).y + (a).y*(b).x; }
#define CROT(w, s) { float _x = (w).x*(s).x - (w).y*(s).y; (w).y = (w).x*(s).y + (w).y*(s).x; (w).x = _x; }

// ---------------- scratch (device globals; no allocation allowed) ----------------
static __device__ double dd_df[41];                  // factorials
static __device__ double dd_wq[128];
static __device__ float  dd_ws2[128 * 400];          // [b][col]
static __device__ float2 dd_Fk[24 * 400];            // [p][col]
static __device__ float  dd_dinv[40 * NC];           // [b][cidx]  (2l+1)*d^l_{m,n}, m>=0
static __device__ float2 dd_XF[16 * 16 * 20 * 128];  // [(z*16+i)][m(0..19)][b]
static __device__ float2 dd_G[16 * 16 * 400];        // [(z*16+i)][col]
static __device__ float2 dd_Y[32 * 16 * 400];        // conj(y)*SCALING: [o][i][col]  (i-major)
static __device__ float2 dd_ZL[512 * NC];            // [(z*32+o)][cidx], m>=0 only
static __device__ float2 dd_tw40[40];                // e^{+2pi i t/40}
static __device__ float2 dd_tw128[128];              // e^{+2pi i t/128}

// ---------------- Wigner small-d via factorial-ratio recurrence (fp64) ----------------
__device__ double wigner_d_dev(int l, int m, int n, double beta) {
    double cb = cos(0.5 * beta), sb = sin(0.5 * beta);
    int s0 = (n - m) > 0 ? (n - m) : 0;
    int s1 = (l + n) < (l - m) ? (l + n) : (l - m);
    if (s1 < s0) return 0.0;
    double pref = sqrt(dd_df[l + m]) * sqrt(dd_df[l - m]) * sqrt(dd_df[l + n]) * sqrt(dd_df[l - n]);
    double t = pref / (dd_df[l + n - s0] * dd_df[s0] * dd_df[m - n + s0] * dd_df[l - m - s0]);
    int ec = 2 * l + n - m - 2 * s0;
    int es = m - n + 2 * s0;
    for (int k = 0; k < ec; k++) t *= cb;
    for (int k = 0; k < es; k++) t *= sb;
    if ((m - n + s0) & 1) t = -t;
    double v = t;
    double r2 = (sb * sb) / (cb * cb);
    for (int s = s0; s < s1; s++) {
        t *= -r2 * (double)((l + n - s) * (l - m - s)) / (double)((s + 1) * (m - n + s + 1));
        v += t;
    }
    return v;
}

__device__ __forceinline__ int col_to_l(int col) {
    int l = (int)sqrtf((float)col);
    while ((l + 1) * (l + 1) <= col) l++;
    while (l * l > col) l--;
    return l;
}

// decode compact cidx -> (l, m>=0, ni)
__device__ __forceinline__ void decode_c(int c, int& l, int& m, int& ni) {
    l = 0;
    while (c >= (l + 1) * (2 * l + 1)) { c -= (l + 1) * (2 * l + 1); l++; }
    int w = 2 * l + 1;
    m = c / w;
    ni = c - m * w;
}

// cum2(l) = sum_{j<l} (j+1)(2j+1)
__device__ __forceinline__ int cum2f(int l) {
    return (l - 1) * l * (2 * l - 1) / 3 + 3 * l * (l - 1) / 2 + l;
}

// ---------------- stage 0: tables ----------------
__global__ void k_setup() {
    int t = threadIdx.x;
    if (t < 41) {
        double f = 1.0;
        for (int k = 2; k <= t; k++) f *= (double)k;
        dd_df[t] = f;
    }
    if (t < 40) {
        double a = 2.0 * PI_D * t / 40.0;
        dd_tw40[t] = make_float2((float)cos(a), (float)sin(a));
    }
    if (t < 128) {
        double a = 2.0 * PI_D * t / 128.0;
        dd_tw128[t] = make_float2((float)cos(a), (float)sin(a));
        double th = PI_D * (2 * t + 1) / 256.0;
        double s = 0.0;
        for (int k = 0; k < 64; k++) s += sin((2.0 * k + 1.0) * th) / (2.0 * k + 1.0);
        dd_wq[t] = (2.0 / 64.0) * sin(th) * s;
    }
}

__global__ void k_ws2() {
    int idx = blockIdx.x * blockDim.x + threadIdx.x;
    if (idx >= 128 * 400) return;
    int b = idx / 400, col = idx - b * 400;
    int l = col_to_l(col);
    int m = col - l * l - l;
    double beta = PI_D * (2 * b + 1) / 256.0;
    dd_ws2[idx] = (float)(wigner_d_dev(l, m, 0, beta) * dd_wq[b]);
}

__global__ void k_Fk() {
    int idx = blockIdx.x * blockDim.x + threadIdx.x;
    if (idx >= 24 * 400) return;
    int p = idx / 400, col = idx - p * 400;
    int l = col_to_l(col);
    int m = col - l * l - l;
    double beta = (double)(p / 8 + 1) * PI_D / 24.0;
    double alpha = (double)(p % 8) * (PI_D / 4.0);
    double d = wigner_d_dev(l, m, 0, beta);
    dd_Fk[idx] = make_float2((float)(d * cos(m * alpha)), (float)(-d * sin(m * alpha)));
}

__global__ void k_dinv() {
    int idx = blockIdx.x * blockDim.x + threadIdx.x;
    if (idx >= 40 * NC) return;
    int b = idx / NC, c = idx - b * NC;
    int l, m, ni;
    decode_c(c, l, m, ni);
    double beta = PI_D * (2 * b + 1) / 80.0;
    dd_dinv[idx] = (float)((double)(2 * l + 1) * wigner_d_dev(l, m, ni - l, beta));
}

// ---------------- stage 1: alpha-DFT (20 non-negative bins), one block per (z,i) ----------------
__global__ void k_XF(const float* __restrict__ x) {
    __shared__ float2 twT[128 * 20];   // [a][m], e^{-2pi i m a/128} stored as (cos,-sin)
    __shared__ float  xs[12][129];     // padded rows
    int zi = blockIdx.x;
    int t = threadIdx.x;               // 256 threads
    for (int i = t; i < 128 * 20; i += 256) {
        int a = i / 20, mi = i - a * 20;
        float2 w = dd_tw128[(a * mi) & 127];
        twT[i] = make_float2(w.x, -w.y);
    }
    const float* xp = x + (size_t)zi * 128 * 128;
    for (int chunk = 0; chunk < 11; chunk++) {
        int b0 = chunk * 12;
        __syncthreads();
        for (int i = t; i < 12 * 128; i += 256) {
            int r = i >> 7, a = i & 127;
            if (b0 + r < 128) xs[r][a] = xp[(size_t)(b0 + r) * 128 + a];
        }
        __syncthreads();
        if (t < 240) {
            int r = t / 20, mi = t - r * 20;
            int b = b0 + r;
            if (b < 128) {
                float re = 0.f, im = 0.f;
                #pragma unroll 8
                for (int a = 0; a < 128; a++) {
                    float v = xs[r][a];
                    float2 w = twT[a * 20 + mi];
                    re += v * w.x;
                    im += v * w.y;
                }
                dd_XF[((size_t)zi * 20 + mi) * 128 + b] = make_float2(re, im);
            }
        }
    }
}

// ---------------- stage 2: S2 analysis (negative m via conjugate) ----------------
__global__ void k_G() {
    int idx = blockIdx.x * blockDim.x + threadIdx.x;
    if (idx >= 16 * 16 * 400) return;
    int zi = idx / 400, col = idx - zi * 400;
    int l = col_to_l(col);
    int m = col - l * l - l;
    int am = m < 0 ? -m : m;
    float sgn = m < 0 ? -1.f : 1.f;
    const float2* xf = &dd_XF[((size_t)zi * 20 + am) * 128];
    float re = 0.f, im = 0.f;
    #pragma unroll 4
    for (int b = 0; b < 128; b++) {
        float w = dd_ws2[b * 400 + col];
        float2 v = xf[b];
        re += w * v.x;
        im += w * v.y;
    }
    dd_G[idx] = make_float2(re, sgn * im);
}

// ---------------- stage 3: kernel spectrum (store conj * SCALING), i-major layout ----------------
__global__ void k_Y(const float* __restrict__ ker) {
    int idx = blockIdx.x * blockDim.x + threadIdx.x;
    if (idx >= 32 * 16 * 400) return;
    int o = idx / 6400;
    int r = idx - o * 6400;
    int i = r / 400, col = r - i * 400;
    const float* kp = ker + ((size_t)i * 32 + o) * 24;
    float re = 0.f, im = 0.f;
    #pragma unroll
    for (int p = 0; p < 24; p++) {
        float2 f = dd_Fk[p * 400 + col];
        float kv = kp[p];
        re += kv * f.x;
        im += kv * f.y;
    }
    dd_Y[idx] = make_float2(SCALING_F * re, -SCALING_F * im);
}

// ---------------- stage 4: per-(z,o) SO(3) spectrum (m>=0 only) ----------------
__global__ void k_ZL() {
    extern __shared__ float2 smzl[];
    float2* Gs = smzl;            // 6400: [i][col] for this z
    float2* Ys = smzl + 6400;     // 6400: [i][col] for this o (already conj)
    int bi = blockIdx.x;
    int z = bi >> 5, o = bi & 31;
    int tid = threadIdx.x;
    for (int i = tid; i < 6400; i += blockDim.x) {
        Gs[i] = dd_G[z * 6400 + i];
        Ys[i] = dd_Y[o * 6400 + i];
    }
    __syncthreads();
    for (int cidx = tid; cidx < NC; cidx += blockDim.x) {
        int l, m, ni;
        decode_c(cidx, l, m, ni);
        int colm = l * l + l + m;      // m >= 0
        int coln = l * l + ni;
        float re = 0.f, im = 0.f;
        #pragma unroll
        for (int i = 0; i < 16; i++) {
            float2 a = Gs[i * 400 + colm];
            float2 yb = Ys[i * 400 + coln];
            re += a.x * yb.x - a.y * yb.y;
            im += a.x * yb.y + a.y * yb.x;
        }
        dd_ZL[(size_t)bi * NC + cidx] = make_float2(re, im);
    }
}

// ---------------- stage 5+6 fused: beta synthesis + Hermitian 2D inverse DFT ----------------
// R5 structure (measured 657us): grid = 512 (z,o) x 4 beta-quarters, 2 betas per chunk.
// This round: Ms/Ts row stride 42 (16B alignment) -> float4 LDS, and 2-wide unrolled
// inner loops with twin phasors (wA odd-term, wB even-term, both stepped by s^2).
// SMEM: zls (5530) | Ms (2*20*42) | Ts (2*20*42) | twl (40) = 8930 float2 = 71440 B.
__global__ void __launch_bounds__(256) k_OUT(const float* __restrict__ bias, float* __restrict__ out) {
    extern __shared__ float2 sm[];
    float2* zls = sm;                       // 5530
    float2* Ms  = sm + NC;                  // 2*840 = 1680, row stride 42
    float2* Ts  = Ms + 1680;                // 1680, row stride 42
    float2* twl = Ts + 1680;                // 40
    int bi = blockIdx.x >> 2;
    int quarter = blockIdx.x & 3;
    int o = bi & 31;
    int tid = threadIdx.x;
    for (int i = tid; i < NC; i += 256) zls[i] = dd_ZL[(size_t)bi * NC + i];
    if (tid < 40) twl[tid] = dd_tw40[tid];
    float bv = bias[o];
    __syncthreads();
    float* outp = out + (size_t)bi * 64000;

    for (int chunk = 0; chunk < 5; chunk++) {
        int b0 = quarter * 10 + chunk * 2;
        // ---- M-stage: M[bl,m,nni] = sum_l zl[l,m,n]*dinv[l,b,m,n], m>=0 ----
        for (int p = tid; p < 2 * 780; p += 256) {
            int bl = p / 780, q = p - bl * 780;
            int m = q / 39, nni = q - m * 39;
            int n = nni - 19;
            int an = n < 0 ? -n : n;
            int lmin = m > an ? m : an;
            int cum = cum2f(lmin);
            const float* dv = &dd_dinv[(size_t)(b0 + bl) * NC];
            float re = 0.f, im = 0.f;
            for (int l = lmin; l < 20; l++) {
                int w = 2 * l + 1;
                int cidx = cum + m * w + (n + l);
                float d = dv[cidx];
                float2 zv = zls[cidx];
                re += zv.x * d;
                im += zv.y * d;
                cum += (l + 1) * w;
            }
            Ms[(bl * 20 + m) * 42 + nni] = make_float2(re, im);
        }
        __syncthreads();
        // ---- T-stage: T[m,g] = sum_n M[m,n] e^{+i n g th}; g and g+20 via n-parity ----
        // 200 tiles: bl(2) x tm(10) x tg(10); tile = 2m x 2g; 2-nn unrolled, float4 loads
        for (int tt = tid; tt < 200; tt += 256) {
            int bl = tt / 100, r = tt - bl * 100;
            int tm = r / 10, tg = r - tm * 10;
            int m0 = tm * 2, g0 = tg * 2;
            const float4* M0 = reinterpret_cast<const float4*>(&Ms[(bl * 20 + m0) * 42]);
            const float4* M1 = reinterpret_cast<const float4*>(&Ms[(bl * 20 + m0 + 1) * 42]);
            float2 wA0 = twl[(21 * g0) % 40];         // nn=0 phase (n=-19)
            float2 wA1 = twl[(21 * (g0 + 1)) % 40];
            float2 s0 = twl[g0], s1 = twl[g0 + 1];
            float2 wB0 = wA0; CROT(wB0, s0);          // nn=1 phase
            float2 wB1 = wA1; CROT(wB1, s1);
            float2 s0q = s0; CROT(s0q, s0);           // step^2
            float2 s1q = s1; CROT(s1q, s1);
            float2 aE00 = {0,0}, aE01 = {0,0}, aE10 = {0,0}, aE11 = {0,0};
            float2 aO00 = {0,0}, aO01 = {0,0}, aO10 = {0,0}, aO11 = {0,0};
            #pragma unroll
            for (int k = 0; k < 19; k++) {
                float4 u0 = M0[k];     // nn=2k (x,y), nn=2k+1 (z,w)
                float4 u1 = M1[k];
                float2 ea = make_float2(u0.x, u0.y), eb = make_float2(u0.z, u0.w);
                float2 fa = make_float2(u1.x, u1.y), fb = make_float2(u1.z, u1.w);
                // nn even -> n odd -> aO with wA
                CMADD(aO00, ea, wA0); CMADD(aO01, ea, wA1);
                CMADD(aO10, fa, wA0); CMADD(aO11, fa, wA1);
                // nn odd -> n even -> aE with wB
                CMADD(aE00, eb, wB0); CMADD(aE01, eb, wB1);
                CMADD(aE10, fb, wB0); CMADD(aE11, fb, wB1);
                CROT(wA0, s0q); CROT(wA1, s1q); CROT(wB0, s0q); CROT(wB1, s1q);
            }
            {   // tail nn=38 (even -> aO with wA, now at phase n=+19)
                float2 ea = Ms[(bl * 20 + m0) * 42 + 38];
                float2 fa = Ms[(bl * 20 + m0 + 1) * 42 + 38];
                CMADD(aO00, ea, wA0); CMADD(aO01, ea, wA1);
                CMADD(aO10, fa, wA0); CMADD(aO11, fa, wA1);
            }
            float2* T0 = &Ts[(bl * 20 + m0) * 42];
            float2* T1 = T0 + 42;
            T0[g0]      = make_float2(aE00.x + aO00.x, aE00.y + aO00.y);
            T0[g0 + 1]  = make_float2(aE01.x + aO01.x, aE01.y + aO01.y);
            T0[g0 + 20] = make_float2(aE00.x - aO00.x, aE00.y - aO00.y);
            T0[g0 + 21] = make_float2(aE01.x - aO01.x, aE01.y - aO01.y);
            T1[g0]      = make_float2(aE10.x + aO10.x, aE10.y + aO10.y);
            T1[g0 + 1]  = make_float2(aE11.x + aO11.x, aE11.y + aO11.y);
            T1[g0 + 20] = make_float2(aE10.x - aO10.x, aE10.y - aO10.y);
            T1[g0 + 21] = make_float2(aE11.x - aO11.x, aE11.y - aO11.y);
        }
        __syncthreads();
        // ---- f-stage: f[a,g] = bv + T[0,g].re + 2 sum_{m>=1} Re(T[m,g] e^{i m a th});
        //      a and a+20 via m-parity. 400 tiles: bl(2) x ta(10) x tg(20); tile = 2a x 2g;
        //      2-m unrolled, float4 loads.
        for (int tt = tid; tt < 400; tt += 256) {
            int bl = tt / 200, r = tt - bl * 200;
            int ta = r / 20, tg = r - ta * 20;
            int a0 = ta * 2, g0 = tg * 2;
            const float2* Tb = &Ts[(bl * 20) * 42];
            float2 wA0 = twl[a0], wA1 = twl[a0 + 1];   // m=1
            float2 st0 = wA0, st1 = wA1;
            float2 wB0 = wA0; CROT(wB0, st0);          // m=2
            float2 wB1 = wA1; CROT(wB1, st1);
            float2 st0q = st0; CROT(st0q, st0);        // step^2
            float2 st1q = st1; CROT(st1q, st1);
            float sO00 = 0.f, sO01 = 0.f, sO10 = 0.f, sO11 = 0.f;
            float sE00 = 0.f, sE01 = 0.f, sE10 = 0.f, sE11 = 0.f;
            #pragma unroll
            for (int k = 0; k < 9; k++) {
                float4 u = *reinterpret_cast<const float4*>(&Tb[(2 * k + 1) * 42 + g0]);
                float4 v = *reinterpret_cast<const float4*>(&Tb[(2 * k + 2) * 42 + g0]);
                // m = 2k+1 odd -> sO with wA
                sO00 += u.x * wA0.x - u.y * wA0.y;   // (a0,   g0)
                sO01 += u.z * wA0.x - u.w * wA0.y;   // (a0,   g0+1)
                sO10 += u.x * wA1.x - u.y * wA1.y;   // (a0+1, g0)
                sO11 += u.z * wA1.x - u.w * wA1.y;
                // m = 2k+2 even -> sE with wB
                sE00 += v.x * wB0.x - v.y * wB0.y;
                sE01 += v.z * wB0.x - v.w * wB0.y;
                sE10 += v.x * wB1.x - v.y * wB1.y;
                sE11 += v.z * wB1.x - v.w * wB1.y;
                CROT(wA0, st0q); CROT(wA1, st1q); CROT(wB0, st0q); CROT(wB1, st1q);
            }
            {   // tail m=19 (odd -> sO with wA)
                float4 u = *reinterpret_cast<const float4*>(&Tb[19 * 42 + g0]);
                sO00 += u.x * wA0.x - u.y * wA0.y;
                sO01 += u.z * wA0.x - u.w * wA0.y;
                sO10 += u.x * wA1.x - u.y * wA1.y;
                sO11 += u.z * wA1.x - u.w * wA1.y;
            }
            float base0 = bv + Tb[g0].x;
            float base1 = bv + Tb[g0 + 1].x;
            float* op = outp + (size_t)(b0 + bl) * 1600;
            *(float2*)&op[a0 * 40 + g0] =
                make_float2(base0 + 2.f * (sE00 + sO00), base1 + 2.f * (sE01 + sO01));
            *(float2*)&op[(a0 + 1) * 40 + g0] =
                make_float2(base0 + 2.f * (sE10 + sO10), base1 + 2.f * (sE11 + sO11));
            *(float2*)&op[(a0 + 20) * 40 + g0] =
                make_float2(base0 + 2.f * (sE00 - sO00), base1 + 2.f * (sE01 - sO01));
            *(float2*)&op[(a0 + 21) * 40 + g0] =
                make_float2(base0 + 2.f * (sE10 - sO10), base1 + 2.f * (sE11 - sO11));
        }
        __syncthreads();
    }
}

// ---------------- launcher ----------------
extern "C" void kernel_launch(void* const* d_in, const int* in_sizes, int n_in,
                              void* d_out, int out_size) {
    const float* x    = (const float*)d_in[0];   // [16,16,128,128]
    const float* ker  = (const float*)d_in[1];   // [16,32,24]
    const float* bias = (const float*)d_in[2];   // [32]
    float* out = (float*)d_out;                  // [16,32,40,40,40]

    cudaFuncSetAttribute(k_ZL,  cudaFuncAttributeMaxDynamicSharedMemorySize, 102400);
    cudaFuncSetAttribute(k_OUT, cudaFuncAttributeMaxDynamicSharedMemorySize, 71440);

    k_setup<<<1, 128>>>();
    k_ws2 <<<200, 256>>>();
    k_Fk  <<<38, 256>>>();
    k_dinv<<<(40 * NC + 255) / 256, 256>>>();
    k_XF  <<<256, 256>>>(x);
    k_G   <<<400, 256>>>();
    k_Y   <<<800, 256>>>(ker);
    k_ZL  <<<512, 256, 102400>>>();
    k_OUT <<<2048, 256, 71440>>>(bias, out);
}